// round 12
// baseline (speedup 1.0000x reference)
#include <cuda_runtime.h>
#include <cuda_bf16.h>
#include <cstdint>

#define BWIN 4096
#define NTOK 49
#define DIMV 256
#define NH   8
#define HD   32
#define MTOT (BWIN*NTOK)              /* 200704 */
#define QSCALE 0.17677669529663687f   /* 32^-0.5 */

// ================= scratch (device globals; no allocation allowed) =========
__device__ __nv_bfloat16 g_xhi[(size_t)MTOT * DIMV];
__device__ __nv_bfloat16 g_xlo[(size_t)MTOT * DIMV];
__device__ __nv_bfloat16 g_chi[(size_t)MTOT * DIMV];
__device__ __nv_bfloat16 g_clo[(size_t)MTOT * DIMV];
__device__ __nv_bfloat16 g_wqh[768 * 256];
__device__ __nv_bfloat16 g_wql[768 * 256];
__device__ __nv_bfloat16 g_wph[256 * 256];
__device__ __nv_bfloat16 g_wpl[256 * 256];
__device__ float g_Q[(size_t)BWIN * NH * NTOK * HD];
__device__ float g_K[(size_t)BWIN * NH * NTOK * HD];
__device__ float g_V[(size_t)BWIN * NH * NTOK * HD];

// ======================= helpers ===========================================
__device__ __forceinline__ uint32_t smem_u32(const void* p) {
    uint32_t a;
    asm("{ .reg .u64 t; cvta.to.shared.u64 t, %1; cvt.u32.u64 %0, t; }" : "=r"(a) : "l"(p));
    return a;
}
__device__ __forceinline__ void cp16(uint32_t sdst, const void* g) {
    asm volatile("cp.async.cg.shared.global [%0], [%1], 16;" :: "r"(sdst), "l"(g));
}
#define CP_COMMIT() asm volatile("cp.async.commit_group;" ::: "memory")

__device__ __forceinline__ void ldsm_x4(uint32_t (&r)[4], uint32_t addr) {
    asm volatile("ldmatrix.sync.aligned.m8n8.x4.shared.b16 {%0,%1,%2,%3}, [%4];"
                 : "=r"(r[0]), "=r"(r[1]), "=r"(r[2]), "=r"(r[3]) : "r"(addr));
}
__device__ __forceinline__ void mma16816(float (&d)[4], const uint32_t (&a)[4],
                                         uint32_t b0, uint32_t b1) {
    asm volatile("mma.sync.aligned.m16n8k16.row.col.f32.bf16.bf16.f32 "
                 "{%0,%1,%2,%3}, {%4,%5,%6,%7}, {%8,%9}, {%0,%1,%2,%3};"
                 : "+f"(d[0]), "+f"(d[1]), "+f"(d[2]), "+f"(d[3])
                 : "r"(a[0]), "r"(a[1]), "r"(a[2]), "r"(a[3]), "r"(b0), "r"(b1));
}

// ======================= split / pack kernels ==============================
__global__ __launch_bounds__(256) void k_split_x(const float* __restrict__ in,
                                                 __nv_bfloat16* __restrict__ hi,
                                                 __nv_bfloat16* __restrict__ lo) {
    size_t gi = ((size_t)blockIdx.x * 256 + threadIdx.x) * 4;
    float4 v = *(const float4*)(in + gi);
    __nv_bfloat16 h0 = __float2bfloat16(v.x), h1 = __float2bfloat16(v.y);
    __nv_bfloat16 h2 = __float2bfloat16(v.z), h3 = __float2bfloat16(v.w);
    __nv_bfloat162 hA = __halves2bfloat162(h0, h1), hB = __halves2bfloat162(h2, h3);
    __nv_bfloat162 lA = __halves2bfloat162(__float2bfloat16(v.x - __bfloat162float(h0)),
                                           __float2bfloat16(v.y - __bfloat162float(h1)));
    __nv_bfloat162 lB = __halves2bfloat162(__float2bfloat16(v.z - __bfloat162float(h2)),
                                           __float2bfloat16(v.w - __bfloat162float(h3)));
    *(__nv_bfloat162*)(hi + gi)     = hA; *(__nv_bfloat162*)(hi + gi + 2) = hB;
    *(__nv_bfloat162*)(lo + gi)     = lA; *(__nv_bfloat162*)(lo + gi + 2) = lB;
}

__global__ __launch_bounds__(256) void k_split_w(const float* __restrict__ w,
                                                 __nv_bfloat16* __restrict__ hi,
                                                 __nv_bfloat16* __restrict__ lo, int N) {
    int i = blockIdx.x * 256 + threadIdx.x;   // over 256*N
    int k = i / N, n = i - k * N;
    float v = w[i];
    __nv_bfloat16 h = __float2bfloat16(v);
    hi[(size_t)n * 256 + k] = h;
    lo[(size_t)n * 256 + k] = __float2bfloat16(v - __bfloat162float(h));
}

// ======================= HMMA GEMM (exact R6 config) =======================
template<int EPI>
__global__ __launch_bounds__(256, 2) void mma_gemm(const float* __restrict__ bias,
                                                   float* __restrict__ out) {
    extern __shared__ char smem[];
    const uint32_t sb = smem_u32(smem);
    constexpr int PITCH = 80;
    constexpr uint32_t TILE = 128 * PITCH;
    constexpr uint32_t STAGE = 4 * TILE;
    constexpr int ITERS = 8;

    const int tid = threadIdx.x;
    const int wid = tid >> 5, lane = tid & 31;
    const int warp_m = wid & 1, warp_n = wid >> 1;

    const __nv_bfloat16* gAh = (EPI ? g_chi : g_xhi) + (size_t)blockIdx.y * 128 * 256;
    const __nv_bfloat16* gAl = (EPI ? g_clo : g_xlo) + (size_t)blockIdx.y * 128 * 256;
    const __nv_bfloat16* gBh = (EPI ? g_wph : g_wqh) + (size_t)blockIdx.x * 128 * 256;
    const __nv_bfloat16* gBl = (EPI ? g_wpl : g_wql) + (size_t)blockIdx.x * 128 * 256;

    float acc[4][4][4];
#pragma unroll
    for (int a = 0; a < 4; a++)
#pragma unroll
        for (int b = 0; b < 4; b++)
#pragma unroll
            for (int c = 0; c < 4; c++) acc[a][b][c] = 0.f;

    const int lr = tid >> 2;
    const int lc = tid & 3;
    auto load_stage = [&](int it, int s) {
        const int k0 = it * 32;
        const uint32_t st = sb + (uint32_t)s * STAGE;
#pragma unroll
        for (int j = 0; j < 8; j++) {
            const __nv_bfloat16* base = (j < 2) ? gAh : (j < 4) ? gAl : (j < 6) ? gBh : gBl;
            int r = lr + (j & 1) * 64;
            cp16(st + (uint32_t)(j >> 1) * TILE + (uint32_t)(r * PITCH + lc * 16),
                 base + (size_t)r * 256 + k0 + lc * 8);
        }
        CP_COMMIT();
    };

    const int a_row = (lane & 7) + 8 * ((lane >> 3) & 1);
    const int a_kb  = ((lane >> 4) & 1) * 16;
    const int b_row = (lane & 7) + 8 * ((lane >> 4) & 1);
    const int b_kb  = ((lane >> 3) & 1) * 16;

    load_stage(0, 0);

    int s = 0;
#pragma unroll 1
    for (int it = 0; it < ITERS; ++it) {
        asm volatile("cp.async.wait_group 0;" ::: "memory");
        __syncthreads();
        if (it + 1 < ITERS) load_stage(it + 1, s ^ 1);

        const uint32_t sAh = sb + (uint32_t)s * STAGE;
        const uint32_t sAl = sAh + TILE;
        const uint32_t sBh = sAl + TILE;
        const uint32_t sBl = sBh + TILE;
#pragma unroll
        for (int h16 = 0; h16 < 2; h16++) {
            const int kb = h16 * 32;
            uint32_t bhi[2][4], blo[2][4];
#pragma unroll
            for (int np = 0; np < 2; np++) {
                uint32_t boff = (uint32_t)((warp_n * 32 + np * 16 + b_row) * PITCH + kb + b_kb);
                ldsm_x4(bhi[np], sBh + boff);
                ldsm_x4(blo[np], sBl + boff);
            }
            uint32_t ahi[4][4], alo[4][4];
#pragma unroll
            for (int mi = 0; mi < 4; mi++) {
                uint32_t aoff = (uint32_t)((warp_m * 64 + mi * 16 + a_row) * PITCH + kb + a_kb);
                ldsm_x4(ahi[mi], sAh + aoff);
                ldsm_x4(alo[mi], sAl + aoff);
            }
#pragma unroll
            for (int mi = 0; mi < 4; mi++) {
                mma16816(acc[mi][0], ahi[mi], bhi[0][0], bhi[0][1]);
                mma16816(acc[mi][1], ahi[mi], bhi[0][2], bhi[0][3]);
                mma16816(acc[mi][2], ahi[mi], bhi[1][0], bhi[1][1]);
                mma16816(acc[mi][3], ahi[mi], bhi[1][2], bhi[1][3]);
            }
#pragma unroll
            for (int mi = 0; mi < 4; mi++) {
                mma16816(acc[mi][0], ahi[mi], blo[0][0], blo[0][1]);
                mma16816(acc[mi][1], ahi[mi], blo[0][2], blo[0][3]);
                mma16816(acc[mi][2], ahi[mi], blo[1][0], blo[1][1]);
                mma16816(acc[mi][3], ahi[mi], blo[1][2], blo[1][3]);
            }
#pragma unroll
            for (int mi = 0; mi < 4; mi++) {
                mma16816(acc[mi][0], alo[mi], bhi[0][0], bhi[0][1]);
                mma16816(acc[mi][1], alo[mi], bhi[0][2], bhi[0][3]);
                mma16816(acc[mi][2], alo[mi], bhi[1][0], bhi[1][1]);
                mma16816(acc[mi][3], alo[mi], bhi[1][2], bhi[1][3]);
            }
        }
        s ^= 1;
    }

    const int row0 = blockIdx.y * 128 + warp_m * 64;
    const int col0 = blockIdx.x * 128 + warp_n * 32;

    if (EPI == 1) {
#pragma unroll
        for (int mi = 0; mi < 4; mi++) {
#pragma unroll
            for (int ni = 0; ni < 4; ni++) {
                int col = col0 + ni * 8 + (lane & 3) * 2;
                float bx0 = bias[col], bx1 = bias[col + 1];
                int r0 = row0 + mi * 16 + (lane >> 2);
                float2 v0 = make_float2(acc[mi][ni][0] + bx0, acc[mi][ni][1] + bx1);
                float2 v1 = make_float2(acc[mi][ni][2] + bx0, acc[mi][ni][3] + bx1);
                *(float2*)(out + (size_t)r0 * 256 + col)       = v0;
                *(float2*)(out + (size_t)(r0 + 8) * 256 + col) = v1;
            }
        }
    } else {
#pragma unroll
        for (int mi = 0; mi < 4; mi++) {
#pragma unroll
            for (int ni = 0; ni < 4; ni++) {
#pragma unroll
                for (int id = 0; id < 4; id++) {
                    int row = row0 + mi * 16 + (lane >> 2) + 8 * (id >> 1);
                    int col = col0 + ni * 8 + (lane & 3) * 2 + (id & 1);
                    float v = acc[mi][ni][id] + bias[col];
                    int s2 = col % 3;
                    int hd = col / 3;
                    int h = hd >> 5, d = hd & 31;
                    int b = row / 49, n = row - b * 49;
                    size_t addr = (size_t)(b * NH + h) * (NTOK * HD) + n * HD + d;
                    if (s2 == 0)      g_Q[addr] = v * QSCALE;
                    else if (s2 == 1) g_K[addr] = v;
                    else              g_V[addr] = v;
                }
            }
        }
    }
}

// ======================= attention v4b: reg-cached K, reg P, aligned smem ==
#define KPITCH 33
__global__ __launch_bounds__(256)
void attn_kernel(const int* __restrict__ mask, const float* __restrict__ bias_table)
{
    __shared__ __align__(16) float sQ[NTOK * HD];
    __shared__ __align__(16) float sK[NTOK * KPITCH + 3];   // pad to 16B multiple
    __shared__ __align__(16) float sV[NTOK * HD];
    __shared__ __align__(16) float sBias[169 + 3];
    __shared__ __align__(16) float sMask[NTOK * NTOK];

    const int bh = blockIdx.x;
    const int b = bh >> 3, h = bh & 7;
    const int tid = threadIdx.x;
    const int warp = tid >> 5, lane = tid & 31;

    const float4* Qb = (const float4*)(g_Q + (size_t)bh * NTOK * HD);
    const float4* Kb = (const float4*)(g_K + (size_t)bh * NTOK * HD);
    const float4* Vb = (const float4*)(g_V + (size_t)bh * NTOK * HD);
    const int* mbase = mask + (size_t)b * (NTOK * NTOK);

    for (int i = tid; i < NTOK * 8; i += 256) {
        ((float4*)sQ)[i] = Qb[i];
        ((float4*)sV)[i] = Vb[i];
        float4 kv = Kb[i];
        int r = i >> 3, c = (i & 7) << 2;
        sK[r * KPITCH + c]     = kv.x;
        sK[r * KPITCH + c + 1] = kv.y;
        sK[r * KPITCH + c + 2] = kv.z;
        sK[r * KPITCH + c + 3] = kv.w;
    }
#pragma unroll
    for (int i = tid; i < NTOK * NTOK; i += 256)
        sMask[i] = (1.0f - (float)mbase[i]) * (-1e10f);
    if (tid < 169) sBias[tid] = bias_table[tid * NH + h];
    __syncthreads();

    // per-lane K rows in registers
    const int k0 = lane, k1 = lane + 32;
    const bool v1 = (k1 < NTOK);
    float k0r[HD], k1r[HD];
#pragma unroll
    for (int d = 0; d < HD; d++) k0r[d] = sK[k0 * KPITCH + d];
    const int k1c = v1 ? k1 : k0;
#pragma unroll
    for (int d = 0; d < HD; d++) k1r[d] = sK[k1c * KPITCH + d];

    const int ki0 = k0 / 7, kj0 = k0 - ki0 * 7;
    const int ki1 = k1 / 7, kj1 = k1 - ki1 * 7;

    // this warp's query rows: q = warp + 8*j
    const int nrows = (warp == 0) ? 7 : 6;
    float p0[7], p1[7];

#pragma unroll
    for (int j = 0; j < 7; j++) {
        if (j >= nrows) break;
        const int q = warp + 8 * j;
        const float* qrow = sQ + q * HD;
        float s0 = 0.f, s1 = 0.f;
#pragma unroll
        for (int d = 0; d < HD; d++) {
            float qv = qrow[d];                 // broadcast
            s0 = fmaf(qv, k0r[d], s0);
            s1 = fmaf(qv, k1r[d], s1);
        }
        const int qi = q / 7, qj = q - qi * 7;
        s0 += sBias[(qi - ki0 + 6) * 13 + (qj - kj0 + 6)] + sMask[q * NTOK + k0];
        if (v1) s1 += sBias[(qi - ki1 + 6) * 13 + (qj - kj1 + 6)] + sMask[q * NTOK + k1];
        else    s1 = -3.0e38f;

        float mx = fmaxf(s0, s1);
#pragma unroll
        for (int off = 16; off; off >>= 1)
            mx = fmaxf(mx, __shfl_xor_sync(0xffffffffu, mx, off));
        float e0 = __expf(s0 - mx);
        float e1 = v1 ? __expf(s1 - mx) : 0.f;
        float sum = e0 + e1;
#pragma unroll
        for (int off = 16; off; off >>= 1)
            sum += __shfl_xor_sync(0xffffffffu, sum, off);
        float inv = 1.0f / sum;
        p0[j] = e0 * inv;
        p1[j] = e1 * inv;
    }

    // PV: lane owns output dim d = lane; V read once per warp
    float acc[7];
#pragma unroll
    for (int j = 0; j < 7; j++) acc[j] = 0.f;

#pragma unroll
    for (int k = 0; k < 32; k++) {
        float v = sV[k * HD + lane];
#pragma unroll
        for (int j = 0; j < 7; j++) {
            if (j >= nrows) break;
            float pk = __shfl_sync(0xffffffffu, p0[j], k);
            acc[j] = fmaf(pk, v, acc[j]);
        }
    }
#pragma unroll
    for (int k = 32; k < NTOK; k++) {
        float v = sV[k * HD + lane];
#pragma unroll
        for (int j = 0; j < 7; j++) {
            if (j >= nrows) break;
            float pk = __shfl_sync(0xffffffffu, p1[j], k - 32);
            acc[j] = fmaf(pk, v, acc[j]);
        }
    }

    __nv_bfloat16* chiw = g_chi + ((size_t)b * NTOK) * DIMV + h * HD + lane;
    __nv_bfloat16* clow = g_clo + ((size_t)b * NTOK) * DIMV + h * HD + lane;
#pragma unroll
    for (int j = 0; j < 7; j++) {
        if (j >= nrows) break;
        const int q = warp + 8 * j;
        float s = acc[j];
        __nv_bfloat16 hv = __float2bfloat16(s);
        chiw[(size_t)q * DIMV] = hv;
        clow[(size_t)q * DIMV] = __float2bfloat16(s - __bfloat162float(hv));
    }
}

// ============================================================================
extern "C" void kernel_launch(void* const* d_in, const int* in_sizes, int n_in,
                              void* d_out, int out_size)
{
    const float* x       = (const float*)d_in[0];
    const int*   mask    = (const int*)d_in[1];
    const float* qkv_w   = (const float*)d_in[2];
    const float* qkv_b   = (const float*)d_in[3];
    const float* proj_w  = (const float*)d_in[4];
    const float* proj_b  = (const float*)d_in[5];
    const float* rel_tbl = (const float*)d_in[6];
    float* out = (float*)d_out;

    __nv_bfloat16 *xhi, *xlo, *wqh, *wql, *wph, *wpl;
    cudaGetSymbolAddress((void**)&xhi, g_xhi);
    cudaGetSymbolAddress((void**)&xlo, g_xlo);
    cudaGetSymbolAddress((void**)&wqh, g_wqh);
    cudaGetSymbolAddress((void**)&wql, g_wql);
    cudaGetSymbolAddress((void**)&wph, g_wph);
    cudaGetSymbolAddress((void**)&wpl, g_wpl);

    constexpr int SMEMB = 2 * 4 * 128 * 80;    // 81920
    cudaFuncSetAttribute(mma_gemm<0>, cudaFuncAttributeMaxDynamicSharedMemorySize, SMEMB);
    cudaFuncSetAttribute(mma_gemm<1>, cudaFuncAttributeMaxDynamicSharedMemorySize, SMEMB);

    k_split_x<<<MTOT * 256 / 1024, 256>>>(x, xhi, xlo);
    k_split_w<<<768, 256>>>(qkv_w, wqh, wql, 768);
    k_split_w<<<256, 256>>>(proj_w, wph, wpl, 256);

    mma_gemm<0><<<dim3(6, MTOT / 128), 256, SMEMB>>>(qkv_b, nullptr);

    attn_kernel<<<BWIN * NH, 256>>>(mask, rel_tbl);

    mma_gemm<1><<<dim3(2, MTOT / 128), 256, SMEMB>>>(proj_b, out);
}

// round 13
// speedup vs baseline: 1.2233x; 1.2233x over previous
#include <cuda_runtime.h>
#include <cuda_fp16.h>
#include <cstdint>

#define BWIN 4096
#define NTOK 49
#define DIMV 256
#define NH   8
#define HD   32
#define MTOT (BWIN*NTOK)              /* 200704 */
#define QSCALE 0.17677669529663687f   /* 32^-0.5 */

// ================= scratch (device globals; no allocation allowed) =========
__device__ __half g_xhi[(size_t)MTOT * DIMV];
__device__ __half g_xlo[(size_t)MTOT * DIMV];
__device__ __half g_chi[(size_t)MTOT * DIMV];
__device__ __half g_clo[(size_t)MTOT * DIMV];
__device__ __half g_wq[768 * 256];
__device__ __half g_wp[256 * 256];
__device__ float g_Q[(size_t)BWIN * NH * NTOK * HD];
__device__ float g_K[(size_t)BWIN * NH * NTOK * HD];
__device__ float g_V[(size_t)BWIN * NH * NTOK * HD];

// ======================= helpers ===========================================
__device__ __forceinline__ uint32_t smem_u32(const void* p) {
    uint32_t a;
    asm("{ .reg .u64 t; cvta.to.shared.u64 t, %1; cvt.u32.u64 %0, t; }" : "=r"(a) : "l"(p));
    return a;
}
__device__ __forceinline__ void cp16(uint32_t sdst, const void* g) {
    asm volatile("cp.async.cg.shared.global [%0], [%1], 16;" :: "r"(sdst), "l"(g));
}
#define CP_COMMIT() asm volatile("cp.async.commit_group;" ::: "memory")

__device__ __forceinline__ void ldsm_x4(uint32_t (&r)[4], uint32_t addr) {
    asm volatile("ldmatrix.sync.aligned.m8n8.x4.shared.b16 {%0,%1,%2,%3}, [%4];"
                 : "=r"(r[0]), "=r"(r[1]), "=r"(r[2]), "=r"(r[3]) : "r"(addr));
}
__device__ __forceinline__ void mma16816(float (&d)[4], const uint32_t (&a)[4],
                                         uint32_t b0, uint32_t b1) {
    asm volatile("mma.sync.aligned.m16n8k16.row.col.f32.f16.f16.f32 "
                 "{%0,%1,%2,%3}, {%4,%5,%6,%7}, {%8,%9}, {%0,%1,%2,%3};"
                 : "+f"(d[0]), "+f"(d[1]), "+f"(d[2]), "+f"(d[3])
                 : "r"(a[0]), "r"(a[1]), "r"(a[2]), "r"(a[3]), "r"(b0), "r"(b1));
}

// ======================= split / pack kernels ==============================
__global__ __launch_bounds__(256) void k_split_x(const float* __restrict__ in,
                                                 __half* __restrict__ hi,
                                                 __half* __restrict__ lo) {
    size_t gi = ((size_t)blockIdx.x * 256 + threadIdx.x) * 4;
    float4 v = *(const float4*)(in + gi);
    __half h0 = __float2half(v.x), h1 = __float2half(v.y);
    __half h2 = __float2half(v.z), h3 = __float2half(v.w);
    __half l0 = __float2half(v.x - __half2float(h0));
    __half l1 = __float2half(v.y - __half2float(h1));
    __half l2 = __float2half(v.z - __half2float(h2));
    __half l3 = __float2half(v.w - __half2float(h3));
    *(__half2*)(hi + gi)     = __halves2half2(h0, h1);
    *(__half2*)(hi + gi + 2) = __halves2half2(h2, h3);
    *(__half2*)(lo + gi)     = __halves2half2(l0, l1);
    *(__half2*)(lo + gi + 2) = __halves2half2(l2, l3);
}

// w [256,N] fp32 -> [N,256] fp16 single (k-major, transposed)
__global__ __launch_bounds__(256) void k_split_w(const float* __restrict__ w,
                                                 __half* __restrict__ hi, int N) {
    int i = blockIdx.x * 256 + threadIdx.x;   // over 256*N
    int k = i / N, n = i - k * N;
    hi[(size_t)n * 256 + k] = __float2half(w[i]);
}

// ======================= HMMA GEMM (2-term fp16) ===========================
// C tile 128x128 = (Ahi+Alo)[M,256]*B[N,256]^T, fp16 2-term compensated.
// BK=32, 2-stage cp.async double buffer, 256 threads, 2 CTAs/SM.
template<int EPI>
__global__ __launch_bounds__(256, 2) void mma_gemm(const float* __restrict__ bias,
                                                   float* __restrict__ out) {
    extern __shared__ char smem[];
    const uint32_t sb = smem_u32(smem);
    constexpr int PITCH = 80;
    constexpr uint32_t TILE = 128 * PITCH;        // 10240 B
    constexpr uint32_t STAGE = 3 * TILE;          // Ahi, Alo, B
    constexpr int ITERS = 8;

    const int tid = threadIdx.x;
    const int wid = tid >> 5, lane = tid & 31;
    const int warp_m = wid & 1, warp_n = wid >> 1;

    const __half* gAh = (EPI ? g_chi : g_xhi) + (size_t)blockIdx.y * 128 * 256;
    const __half* gAl = (EPI ? g_clo : g_xlo) + (size_t)blockIdx.y * 128 * 256;
    const __half* gB  = (EPI ? g_wp  : g_wq)  + (size_t)blockIdx.x * 128 * 256;

    float acc[4][4][4];
#pragma unroll
    for (int a = 0; a < 4; a++)
#pragma unroll
        for (int b = 0; b < 4; b++)
#pragma unroll
            for (int c = 0; c < 4; c++) acc[a][b][c] = 0.f;

    const int lr = tid >> 2;
    const int lc = tid & 3;
    auto load_stage = [&](int it, int s) {
        const int k0 = it * 32;
        const uint32_t st = sb + (uint32_t)s * STAGE;
#pragma unroll
        for (int j = 0; j < 6; j++) {
            const __half* base = (j < 2) ? gAh : (j < 4) ? gAl : gB;
            int r = lr + (j & 1) * 64;
            cp16(st + (uint32_t)(j >> 1) * TILE + (uint32_t)(r * PITCH + lc * 16),
                 base + (size_t)r * 256 + k0 + lc * 8);
        }
        CP_COMMIT();
    };

    const int a_row = (lane & 7) + 8 * ((lane >> 3) & 1);
    const int a_kb  = ((lane >> 4) & 1) * 16;
    const int b_row = (lane & 7) + 8 * ((lane >> 4) & 1);
    const int b_kb  = ((lane >> 3) & 1) * 16;

    load_stage(0, 0);

    int s = 0;
#pragma unroll 1
    for (int it = 0; it < ITERS; ++it) {
        asm volatile("cp.async.wait_group 0;" ::: "memory");
        __syncthreads();
        if (it + 1 < ITERS) load_stage(it + 1, s ^ 1);

        const uint32_t sAh = sb + (uint32_t)s * STAGE;
        const uint32_t sAl = sAh + TILE;
        const uint32_t sB  = sAl + TILE;
#pragma unroll
        for (int h16 = 0; h16 < 2; h16++) {
            const int kb = h16 * 32;
            uint32_t bf[2][4];
#pragma unroll
            for (int np = 0; np < 2; np++) {
                uint32_t boff = (uint32_t)((warp_n * 32 + np * 16 + b_row) * PITCH + kb + b_kb);
                ldsm_x4(bf[np], sB + boff);
            }
            uint32_t ahi[4][4], alo[4][4];
#pragma unroll
            for (int mi = 0; mi < 4; mi++) {
                uint32_t aoff = (uint32_t)((warp_m * 64 + mi * 16 + a_row) * PITCH + kb + a_kb);
                ldsm_x4(ahi[mi], sAh + aoff);
                ldsm_x4(alo[mi], sAl + aoff);
            }
#pragma unroll
            for (int mi = 0; mi < 4; mi++) {
                mma16816(acc[mi][0], ahi[mi], bf[0][0], bf[0][1]);
                mma16816(acc[mi][1], ahi[mi], bf[0][2], bf[0][3]);
                mma16816(acc[mi][2], ahi[mi], bf[1][0], bf[1][1]);
                mma16816(acc[mi][3], ahi[mi], bf[1][2], bf[1][3]);
            }
#pragma unroll
            for (int mi = 0; mi < 4; mi++) {
                mma16816(acc[mi][0], alo[mi], bf[0][0], bf[0][1]);
                mma16816(acc[mi][1], alo[mi], bf[0][2], bf[0][3]);
                mma16816(acc[mi][2], alo[mi], bf[1][0], bf[1][1]);
                mma16816(acc[mi][3], alo[mi], bf[1][2], bf[1][3]);
            }
        }
        s ^= 1;
    }

    const int row0 = blockIdx.y * 128 + warp_m * 64;
    const int col0 = blockIdx.x * 128 + warp_n * 32;

    if (EPI == 1) {
#pragma unroll
        for (int mi = 0; mi < 4; mi++) {
#pragma unroll
            for (int ni = 0; ni < 4; ni++) {
                int col = col0 + ni * 8 + (lane & 3) * 2;
                float bx0 = bias[col], bx1 = bias[col + 1];
                int r0 = row0 + mi * 16 + (lane >> 2);
                float2 v0 = make_float2(acc[mi][ni][0] + bx0, acc[mi][ni][1] + bx1);
                float2 v1 = make_float2(acc[mi][ni][2] + bx0, acc[mi][ni][3] + bx1);
                *(float2*)(out + (size_t)r0 * 256 + col)       = v0;
                *(float2*)(out + (size_t)(r0 + 8) * 256 + col) = v1;
            }
        }
    } else {
#pragma unroll
        for (int mi = 0; mi < 4; mi++) {
#pragma unroll
            for (int ni = 0; ni < 4; ni++) {
#pragma unroll
                for (int id = 0; id < 4; id++) {
                    int row = row0 + mi * 16 + (lane >> 2) + 8 * (id >> 1);
                    int col = col0 + ni * 8 + (lane & 3) * 2 + (id & 1);
                    float v = acc[mi][ni][id] + bias[col];
                    int s2 = col % 3;
                    int hd = col / 3;
                    int h = hd >> 5, d = hd & 31;
                    int b = row / 49, n = row - b * 49;
                    size_t addr = (size_t)(b * NH + h) * (NTOK * HD) + n * HD + d;
                    if (s2 == 0)      g_Q[addr] = v * QSCALE;
                    else if (s2 == 1) g_K[addr] = v;
                    else              g_V[addr] = v;
                }
            }
        }
    }
}

// ======================= attention v3 (R10, best) ===========================
#define KPITCH 36
#define PPITCH 52
__global__ __launch_bounds__(256)
void attn_kernel(const int* __restrict__ mask, const float* __restrict__ bias_table)
{
    __shared__ __align__(16) float sQ[NTOK * HD];
    __shared__ __align__(16) float sK[NTOK * KPITCH];
    __shared__ __align__(16) float sV[NTOK * HD];
    __shared__ __align__(16) float sP[NTOK * PPITCH];
    __shared__ __align__(16) float sBias[169 + 3];
    __shared__ __align__(16) float sMask[NTOK * NTOK];

    const int bh = blockIdx.x;
    const int b = bh >> 3, h = bh & 7;
    const int tid = threadIdx.x;
    const int warp = tid >> 5, lane = tid & 31;

    const float4* Qb = (const float4*)(g_Q + (size_t)bh * NTOK * HD);
    const float4* Kb = (const float4*)(g_K + (size_t)bh * NTOK * HD);
    const float4* Vb = (const float4*)(g_V + (size_t)bh * NTOK * HD);
    const int* mbase = mask + (size_t)b * (NTOK * NTOK);

    for (int i = tid; i < NTOK * 8; i += 256) {
        ((float4*)sQ)[i] = Qb[i];
        ((float4*)sV)[i] = Vb[i];
        float4 kv = Kb[i];
        int r = i >> 3, c = (i & 7) << 2;
        *(float4*)(sK + r * KPITCH + c) = kv;
    }
#pragma unroll
    for (int i = tid; i < NTOK * NTOK; i += 256)
        sMask[i] = (1.0f - (float)mbase[i]) * (-1e10f);
    if (tid < 169) sBias[tid] = bias_table[tid * NH + h];
    __syncthreads();

    const int k0 = lane, k1 = lane + 32;
    const bool v1 = (k1 < NTOK);
    const int ki0 = k0 / 7, kj0 = k0 - ki0 * 7;
    const int ki1 = k1 / 7, kj1 = k1 - ki1 * 7;
    const float* kr0 = sK + k0 * KPITCH;
    const float* kr1 = sK + (v1 ? k1 : k0) * KPITCH;

    for (int q = warp; q < NTOK; q += 8) {
        float s0 = 0.f, s1 = 0.f;
        const float* qrow = sQ + q * HD;
#pragma unroll
        for (int d4 = 0; d4 < 8; d4++) {
            float4 qv = *(const float4*)(qrow + d4 * 4);
            float4 a0 = *(const float4*)(kr0 + d4 * 4);
            float4 a1 = *(const float4*)(kr1 + d4 * 4);
            s0 = fmaf(qv.x, a0.x, s0); s1 = fmaf(qv.x, a1.x, s1);
            s0 = fmaf(qv.y, a0.y, s0); s1 = fmaf(qv.y, a1.y, s1);
            s0 = fmaf(qv.z, a0.z, s0); s1 = fmaf(qv.z, a1.z, s1);
            s0 = fmaf(qv.w, a0.w, s0); s1 = fmaf(qv.w, a1.w, s1);
        }
        const int qi = q / 7, qj = q - qi * 7;
        s0 += sBias[(qi - ki0 + 6) * 13 + (qj - kj0 + 6)] + sMask[q * NTOK + k0];
        if (v1) s1 += sBias[(qi - ki1 + 6) * 13 + (qj - kj1 + 6)] + sMask[q * NTOK + k1];
        else    s1 = -3.0e38f;

        float mx = fmaxf(s0, s1);
#pragma unroll
        for (int off = 16; off; off >>= 1)
            mx = fmaxf(mx, __shfl_xor_sync(0xffffffffu, mx, off));
        float e0 = __expf(s0 - mx);
        float e1 = v1 ? __expf(s1 - mx) : 0.f;
        float sum = e0 + e1;
#pragma unroll
        for (int off = 16; off; off >>= 1)
            sum += __shfl_xor_sync(0xffffffffu, sum, off);
        float inv = 1.0f / sum;
        sP[q * PPITCH + k0] = e0 * inv;
        if (v1) sP[q * PPITCH + k1] = e1 * inv;
    }
    __syncthreads();

    __half* chiw = g_chi + ((size_t)b * NTOK) * DIMV + h * HD;
    __half* clow = g_clo + ((size_t)b * NTOK) * DIMV + h * HD;
#pragma unroll 1
    for (int e = tid; e < NTOK * HD; e += 256) {
        int qq = e >> 5, d = e & 31;
        const float* pr = sP + qq * PPITCH;
        float s0 = 0.f, s1 = 0.f;
#pragma unroll
        for (int k = 0; k < 48; k += 2) {
            s0 = fmaf(pr[k],     sV[k * HD + d],       s0);
            s1 = fmaf(pr[k + 1], sV[(k + 1) * HD + d], s1);
        }
        float s = s0 + s1 + pr[48] * sV[48 * HD + d];
        __half hv = __float2half(s);
        chiw[(size_t)qq * DIMV + d] = hv;
        clow[(size_t)qq * DIMV + d] = __float2half(s - __half2float(hv));
    }
}

// ============================================================================
extern "C" void kernel_launch(void* const* d_in, const int* in_sizes, int n_in,
                              void* d_out, int out_size)
{
    const float* x       = (const float*)d_in[0];
    const int*   mask    = (const int*)d_in[1];
    const float* qkv_w   = (const float*)d_in[2];
    const float* qkv_b   = (const float*)d_in[3];
    const float* proj_w  = (const float*)d_in[4];
    const float* proj_b  = (const float*)d_in[5];
    const float* rel_tbl = (const float*)d_in[6];
    float* out = (float*)d_out;

    __half *xhi, *xlo, *wq, *wp;
    cudaGetSymbolAddress((void**)&xhi, g_xhi);
    cudaGetSymbolAddress((void**)&xlo, g_xlo);
    cudaGetSymbolAddress((void**)&wq, g_wq);
    cudaGetSymbolAddress((void**)&wp, g_wp);

    constexpr int SMEMB = 2 * 3 * 128 * 80;    // 61440
    cudaFuncSetAttribute(mma_gemm<0>, cudaFuncAttributeMaxDynamicSharedMemorySize, SMEMB);
    cudaFuncSetAttribute(mma_gemm<1>, cudaFuncAttributeMaxDynamicSharedMemorySize, SMEMB);

    k_split_x<<<MTOT * 256 / 1024, 256>>>(x, xhi, xlo);
    k_split_w<<<768, 256>>>(qkv_w, wq, 768);
    k_split_w<<<256, 256>>>(proj_w, wp, 256);

    mma_gemm<0><<<dim3(6, MTOT / 128), 256, SMEMB>>>(qkv_b, nullptr);

    attn_kernel<<<BWIN * NH, 256>>>(mask, rel_tbl);

    mma_gemm<1><<<dim3(2, MTOT / 128), 256, SMEMB>>>(proj_b, out);
}

// round 14
// speedup vs baseline: 1.3864x; 1.1333x over previous
#include <cuda_runtime.h>
#include <cuda_fp16.h>
#include <cstdint>

#define BWIN 4096
#define NTOK 49
#define DIMV 256
#define NH   8
#define HD   32
#define MTOT (BWIN*NTOK)              /* 200704 */
#define QSCALE 0.17677669529663687f   /* 32^-0.5 */

// ================= scratch (device globals; no allocation allowed) =========
__device__ __half g_xhi[(size_t)MTOT * DIMV];
__device__ __half g_xlo[(size_t)MTOT * DIMV];
__device__ __half g_chi[(size_t)MTOT * DIMV];
__device__ __half g_clo[(size_t)MTOT * DIMV];
__device__ __half g_wq[768 * 256];
__device__ __half g_wp[256 * 256];
__device__ float g_Q[(size_t)BWIN * NH * NTOK * HD];
__device__ float g_K[(size_t)BWIN * NH * NTOK * HD];
__device__ float g_V[(size_t)BWIN * NH * NTOK * HD];

// ======================= helpers ===========================================
__device__ __forceinline__ uint32_t smem_u32(const void* p) {
    uint32_t a;
    asm("{ .reg .u64 t; cvta.to.shared.u64 t, %1; cvt.u32.u64 %0, t; }" : "=r"(a) : "l"(p));
    return a;
}
__device__ __forceinline__ void cp16(uint32_t sdst, const void* g) {
    asm volatile("cp.async.cg.shared.global [%0], [%1], 16;" :: "r"(sdst), "l"(g));
}
#define CP_COMMIT() asm volatile("cp.async.commit_group;" ::: "memory")

__device__ __forceinline__ void ldsm_x4(uint32_t (&r)[4], uint32_t addr) {
    asm volatile("ldmatrix.sync.aligned.m8n8.x4.shared.b16 {%0,%1,%2,%3}, [%4];"
                 : "=r"(r[0]), "=r"(r[1]), "=r"(r[2]), "=r"(r[3]) : "r"(addr));
}
__device__ __forceinline__ void mma16816(float (&d)[4], const uint32_t (&a)[4],
                                         uint32_t b0, uint32_t b1) {
    asm volatile("mma.sync.aligned.m16n8k16.row.col.f32.f16.f16.f32 "
                 "{%0,%1,%2,%3}, {%4,%5,%6,%7}, {%8,%9}, {%0,%1,%2,%3};"
                 : "+f"(d[0]), "+f"(d[1]), "+f"(d[2]), "+f"(d[3])
                 : "r"(a[0]), "r"(a[1]), "r"(a[2]), "r"(a[3]), "r"(b0), "r"(b1));
}
__device__ __forceinline__ uint32_t pack_h2(float x, float y) {
    __half2 h = __halves2half2(__float2half(x), __float2half(y));
    return *(uint32_t*)&h;
}

// ======================= split / pack kernels ==============================
__global__ __launch_bounds__(256) void k_split_x(const float* __restrict__ in,
                                                 __half* __restrict__ hi,
                                                 __half* __restrict__ lo) {
    size_t gi = ((size_t)blockIdx.x * 256 + threadIdx.x) * 4;
    float4 v = *(const float4*)(in + gi);
    __half h0 = __float2half(v.x), h1 = __float2half(v.y);
    __half h2 = __float2half(v.z), h3 = __float2half(v.w);
    __half l0 = __float2half(v.x - __half2float(h0));
    __half l1 = __float2half(v.y - __half2float(h1));
    __half l2 = __float2half(v.z - __half2float(h2));
    __half l3 = __float2half(v.w - __half2float(h3));
    *(__half2*)(hi + gi)     = __halves2half2(h0, h1);
    *(__half2*)(hi + gi + 2) = __halves2half2(h2, h3);
    *(__half2*)(lo + gi)     = __halves2half2(l0, l1);
    *(__half2*)(lo + gi + 2) = __halves2half2(l2, l3);
}

__global__ __launch_bounds__(256) void k_split_w(const float* __restrict__ w,
                                                 __half* __restrict__ hi, int N) {
    int i = blockIdx.x * 256 + threadIdx.x;
    int k = i / N, n = i - k * N;
    hi[(size_t)n * 256 + k] = __float2half(w[i]);
}

// ======================= HMMA GEMM (2-term fp16, R13) ======================
template<int EPI>
__global__ __launch_bounds__(256, 2) void mma_gemm(const float* __restrict__ bias,
                                                   float* __restrict__ out) {
    extern __shared__ char smem[];
    const uint32_t sb = smem_u32(smem);
    constexpr int PITCH = 80;
    constexpr uint32_t TILE = 128 * PITCH;
    constexpr uint32_t STAGE = 3 * TILE;
    constexpr int ITERS = 8;

    const int tid = threadIdx.x;
    const int wid = tid >> 5, lane = tid & 31;
    const int warp_m = wid & 1, warp_n = wid >> 1;

    const __half* gAh = (EPI ? g_chi : g_xhi) + (size_t)blockIdx.y * 128 * 256;
    const __half* gAl = (EPI ? g_clo : g_xlo) + (size_t)blockIdx.y * 128 * 256;
    const __half* gB  = (EPI ? g_wp  : g_wq)  + (size_t)blockIdx.x * 128 * 256;

    float acc[4][4][4];
#pragma unroll
    for (int a = 0; a < 4; a++)
#pragma unroll
        for (int b = 0; b < 4; b++)
#pragma unroll
            for (int c = 0; c < 4; c++) acc[a][b][c] = 0.f;

    const int lr = tid >> 2;
    const int lc = tid & 3;
    auto load_stage = [&](int it, int s) {
        const int k0 = it * 32;
        const uint32_t st = sb + (uint32_t)s * STAGE;
#pragma unroll
        for (int j = 0; j < 6; j++) {
            const __half* base = (j < 2) ? gAh : (j < 4) ? gAl : gB;
            int r = lr + (j & 1) * 64;
            cp16(st + (uint32_t)(j >> 1) * TILE + (uint32_t)(r * PITCH + lc * 16),
                 base + (size_t)r * 256 + k0 + lc * 8);
        }
        CP_COMMIT();
    };

    const int a_row = (lane & 7) + 8 * ((lane >> 3) & 1);
    const int a_kb  = ((lane >> 4) & 1) * 16;
    const int b_row = (lane & 7) + 8 * ((lane >> 4) & 1);
    const int b_kb  = ((lane >> 3) & 1) * 16;

    load_stage(0, 0);

    int s = 0;
#pragma unroll 1
    for (int it = 0; it < ITERS; ++it) {
        asm volatile("cp.async.wait_group 0;" ::: "memory");
        __syncthreads();
        if (it + 1 < ITERS) load_stage(it + 1, s ^ 1);

        const uint32_t sAh = sb + (uint32_t)s * STAGE;
        const uint32_t sAl = sAh + TILE;
        const uint32_t sB  = sAl + TILE;
#pragma unroll
        for (int h16 = 0; h16 < 2; h16++) {
            const int kb = h16 * 32;
            uint32_t bf[2][4];
#pragma unroll
            for (int np = 0; np < 2; np++) {
                uint32_t boff = (uint32_t)((warp_n * 32 + np * 16 + b_row) * PITCH + kb + b_kb);
                ldsm_x4(bf[np], sB + boff);
            }
            uint32_t ahi[4][4], alo[4][4];
#pragma unroll
            for (int mi = 0; mi < 4; mi++) {
                uint32_t aoff = (uint32_t)((warp_m * 64 + mi * 16 + a_row) * PITCH + kb + a_kb);
                ldsm_x4(ahi[mi], sAh + aoff);
                ldsm_x4(alo[mi], sAl + aoff);
            }
#pragma unroll
            for (int mi = 0; mi < 4; mi++) {
                mma16816(acc[mi][0], ahi[mi], bf[0][0], bf[0][1]);
                mma16816(acc[mi][1], ahi[mi], bf[0][2], bf[0][3]);
                mma16816(acc[mi][2], ahi[mi], bf[1][0], bf[1][1]);
                mma16816(acc[mi][3], ahi[mi], bf[1][2], bf[1][3]);
            }
#pragma unroll
            for (int mi = 0; mi < 4; mi++) {
                mma16816(acc[mi][0], alo[mi], bf[0][0], bf[0][1]);
                mma16816(acc[mi][1], alo[mi], bf[0][2], bf[0][3]);
                mma16816(acc[mi][2], alo[mi], bf[1][0], bf[1][1]);
                mma16816(acc[mi][3], alo[mi], bf[1][2], bf[1][3]);
            }
        }
        s ^= 1;
    }

    const int row0 = blockIdx.y * 128 + warp_m * 64;
    const int col0 = blockIdx.x * 128 + warp_n * 32;

    if (EPI == 1) {
#pragma unroll
        for (int mi = 0; mi < 4; mi++) {
#pragma unroll
            for (int ni = 0; ni < 4; ni++) {
                int col = col0 + ni * 8 + (lane & 3) * 2;
                float bx0 = bias[col], bx1 = bias[col + 1];
                int r0 = row0 + mi * 16 + (lane >> 2);
                float2 v0 = make_float2(acc[mi][ni][0] + bx0, acc[mi][ni][1] + bx1);
                float2 v1 = make_float2(acc[mi][ni][2] + bx0, acc[mi][ni][3] + bx1);
                *(float2*)(out + (size_t)r0 * 256 + col)       = v0;
                *(float2*)(out + (size_t)(r0 + 8) * 256 + col) = v1;
            }
        }
    } else {
#pragma unroll
        for (int mi = 0; mi < 4; mi++) {
#pragma unroll
            for (int ni = 0; ni < 4; ni++) {
#pragma unroll
                for (int id = 0; id < 4; id++) {
                    int row = row0 + mi * 16 + (lane >> 2) + 8 * (id >> 1);
                    int col = col0 + ni * 8 + (lane & 3) * 2 + (id & 1);
                    float v = acc[mi][ni][id] + bias[col];
                    int s2 = col % 3;
                    int hd = col / 3;
                    int h = hd >> 5, d = hd & 31;
                    int b = row / 49, n = row - b * 49;
                    size_t addr = (size_t)(b * NH + h) * (NTOK * HD) + n * HD + d;
                    if (s2 == 0)      g_Q[addr] = v * QSCALE;
                    else if (s2 == 1) g_K[addr] = v;
                    else              g_V[addr] = v;
                }
            }
        }
    }
}

// ======================= attention v5: tensor-core ==========================
// One CTA per (window, head). 256 threads: 8 warps stage, 4 warps compute.
// S = QK^T via m16n8k16 (3-term fp16, fp32 acc), softmax in registers,
// P(acc) reused directly as A-fragments for PV (3-term).
__global__ __launch_bounds__(256)
void attn_kernel(const int* __restrict__ mask, const float* __restrict__ bias_table)
{
    // fp16 tiles, pitch 40 halfs (80B) for Q/K, 72 halfs (144B) for VT
    __shared__ __align__(16) __half sQh[64 * 40];
    __shared__ __align__(16) __half sQl[64 * 40];
    __shared__ __align__(16) __half sKh[64 * 40];
    __shared__ __align__(16) __half sKl[64 * 40];
    __shared__ __align__(16) __half sVTh[32 * 72];
    __shared__ __align__(16) __half sVTl[32 * 72];
    __shared__ __align__(16) float sBias[169 + 3];
    __shared__ __align__(16) float sMask[NTOK * NTOK];

    const int bh = blockIdx.x;
    const int b = bh >> 3, h = bh & 7;
    const int tid = threadIdx.x;
    const int warp = tid >> 5, lane = tid & 31;

    const float4* Qb = (const float4*)(g_Q + (size_t)bh * NTOK * HD);
    const float4* Kb = (const float4*)(g_K + (size_t)bh * NTOK * HD);
    const float4* Vb = (const float4*)(g_V + (size_t)bh * NTOK * HD);
    const int* mbase = mask + (size_t)b * (NTOK * NTOK);

    // zero pad rows 49..63 of Q/K tiles (uint32 idx 980..1279 of 64*20)
    for (int i = tid; i < 300; i += 256) {
        ((uint32_t*)sQh)[980 + i] = 0; ((uint32_t*)sQl)[980 + i] = 0;
        ((uint32_t*)sKh)[980 + i] = 0; ((uint32_t*)sKl)[980 + i] = 0;
    }
    // zero VT fully (32*36 uint32 each)
    for (int i = tid; i < 1152; i += 256) {
        ((uint32_t*)sVTh)[i] = 0; ((uint32_t*)sVTl)[i] = 0;
    }
    __syncthreads();

    // stage Q, K (hi/lo), VT (transposed hi/lo)
    for (int i = tid; i < NTOK * 8; i += 256) {
        int r = i >> 3, c = (i & 7) << 2;
        float4 q = Qb[i];
        float4 k = Kb[i];
        float4 v = Vb[i];
        __half qh0 = __float2half(q.x), qh1 = __float2half(q.y);
        __half qh2 = __float2half(q.z), qh3 = __float2half(q.w);
        *(__half2*)&sQh[r * 40 + c]     = __halves2half2(qh0, qh1);
        *(__half2*)&sQh[r * 40 + c + 2] = __halves2half2(qh2, qh3);
        *(__half2*)&sQl[r * 40 + c] = __halves2half2(
            __float2half(q.x - __half2float(qh0)), __float2half(q.y - __half2float(qh1)));
        *(__half2*)&sQl[r * 40 + c + 2] = __halves2half2(
            __float2half(q.z - __half2float(qh2)), __float2half(q.w - __half2float(qh3)));
        __half kh0 = __float2half(k.x), kh1 = __float2half(k.y);
        __half kh2 = __float2half(k.z), kh3 = __float2half(k.w);
        *(__half2*)&sKh[r * 40 + c]     = __halves2half2(kh0, kh1);
        *(__half2*)&sKh[r * 40 + c + 2] = __halves2half2(kh2, kh3);
        *(__half2*)&sKl[r * 40 + c] = __halves2half2(
            __float2half(k.x - __half2float(kh0)), __float2half(k.y - __half2float(kh1)));
        *(__half2*)&sKl[r * 40 + c + 2] = __halves2half2(
            __float2half(k.z - __half2float(kh2)), __float2half(k.w - __half2float(kh3)));
        // VT[d][k] = V[k][d]
        float vv[4] = {v.x, v.y, v.z, v.w};
#pragma unroll
        for (int j = 0; j < 4; j++) {
            __half hv = __float2half(vv[j]);
            sVTh[(c + j) * 72 + r] = hv;
            sVTl[(c + j) * 72 + r] = __float2half(vv[j] - __half2float(hv));
        }
    }
    for (int i = tid; i < NTOK * NTOK; i += 256)
        sMask[i] = (1.0f - (float)mbase[i]) * (-1e10f);
    if (tid < 169) sBias[tid] = bias_table[tid * NH + h];
    __syncthreads();

    if (warp >= 4) return;   // 4 compute warps

    const uint32_t aQh = smem_u32(sQh), aQl = smem_u32(sQl);
    const uint32_t aKh = smem_u32(sKh), aKl = smem_u32(sKl);
    const uint32_t aVh = smem_u32(sVTh), aVl = smem_u32(sVTl);

    const int a_row = (lane & 7) + 8 * ((lane >> 3) & 1);
    const int a_kb  = ((lane >> 4) & 1) * 16;
    const int b_row = (lane & 7) + 8 * ((lane >> 4) & 1);
    const int b_kb  = ((lane >> 3) & 1) * 16;
    const int mrow = warp * 16;

    // ---- S = Q K^T (64x64, this warp: rows mrow..mrow+15) ----
    float s[8][4];
#pragma unroll
    for (int t = 0; t < 8; t++)
#pragma unroll
        for (int id = 0; id < 4; id++) s[t][id] = 0.f;

#pragma unroll
    for (int h16 = 0; h16 < 2; h16++) {
        uint32_t qh[4], ql[4];
        uint32_t aoff = (uint32_t)((mrow + a_row) * 80 + h16 * 32 + a_kb);
        ldsm_x4(qh, aQh + aoff);
        ldsm_x4(ql, aQl + aoff);
#pragma unroll
        for (int t = 0; t < 4; t++) {
            uint32_t kh[4], kl[4];
            uint32_t boff = (uint32_t)((t * 16 + b_row) * 80 + h16 * 32 + b_kb);
            ldsm_x4(kh, aKh + boff);
            ldsm_x4(kl, aKl + boff);
            mma16816(s[2 * t],     qh, kh[0], kh[1]);
            mma16816(s[2 * t + 1], qh, kh[2], kh[3]);
            mma16816(s[2 * t],     ql, kh[0], kh[1]);
            mma16816(s[2 * t + 1], ql, kh[2], kh[3]);
            mma16816(s[2 * t],     qh, kl[0], kl[1]);
            mma16816(s[2 * t + 1], qh, kl[2], kl[3]);
        }
    }

    // ---- bias + mask + oob ----
    const int r0 = mrow + (lane >> 2);        // rows r0, r0+8
    const int c0 = (lane & 3) * 2;
#pragma unroll
    for (int t = 0; t < 8; t++) {
#pragma unroll
        for (int id = 0; id < 4; id++) {
            int q = r0 + 8 * (id >> 1);
            int k = 8 * t + c0 + (id & 1);
            if (k >= NTOK) { s[t][id] = -3.0e38f; continue; }
            if (q < NTOK) {
                int qi = q / 7, qj = q - qi * 7;
                int ki = k / 7, kj = k - ki * 7;
                s[t][id] += sBias[(qi - ki + 6) * 13 + (qj - kj + 6)] + sMask[q * NTOK + k];
            }
        }
    }

    // ---- softmax in registers (row groups of 4 lanes) ----
    {
        float mx0 = -3.0e38f, mx1 = -3.0e38f;
#pragma unroll
        for (int t = 0; t < 8; t++) {
            mx0 = fmaxf(mx0, fmaxf(s[t][0], s[t][1]));
            mx1 = fmaxf(mx1, fmaxf(s[t][2], s[t][3]));
        }
#pragma unroll
        for (int off = 1; off <= 2; off <<= 1) {
            mx0 = fmaxf(mx0, __shfl_xor_sync(0xffffffffu, mx0, off));
            mx1 = fmaxf(mx1, __shfl_xor_sync(0xffffffffu, mx1, off));
        }
        float sum0 = 0.f, sum1 = 0.f;
#pragma unroll
        for (int t = 0; t < 8; t++) {
            s[t][0] = __expf(s[t][0] - mx0); sum0 += s[t][0];
            s[t][1] = __expf(s[t][1] - mx0); sum0 += s[t][1];
            s[t][2] = __expf(s[t][2] - mx1); sum1 += s[t][2];
            s[t][3] = __expf(s[t][3] - mx1); sum1 += s[t][3];
        }
#pragma unroll
        for (int off = 1; off <= 2; off <<= 1) {
            sum0 += __shfl_xor_sync(0xffffffffu, sum0, off);
            sum1 += __shfl_xor_sync(0xffffffffu, sum1, off);
        }
        float i0 = 1.0f / sum0, i1 = 1.0f / sum1;
#pragma unroll
        for (int t = 0; t < 8; t++) {
            s[t][0] *= i0; s[t][1] *= i0;
            s[t][2] *= i1; s[t][3] *= i1;
        }
    }

    // ---- pack P hi/lo into A-fragments (acc layout == A-frag layout) ----
    uint32_t pah[4][4], pal[4][4];
#pragma unroll
    for (int j = 0; j < 4; j++) {
        float v00 = s[2 * j][0],     v01 = s[2 * j][1];
        float v10 = s[2 * j][2],     v11 = s[2 * j][3];
        float v20 = s[2 * j + 1][0], v21 = s[2 * j + 1][1];
        float v30 = s[2 * j + 1][2], v31 = s[2 * j + 1][3];
        pah[j][0] = pack_h2(v00, v01);
        pah[j][1] = pack_h2(v10, v11);
        pah[j][2] = pack_h2(v20, v21);
        pah[j][3] = pack_h2(v30, v31);
        pal[j][0] = pack_h2(v00 - __half2float(__float2half(v00)),
                            v01 - __half2float(__float2half(v01)));
        pal[j][1] = pack_h2(v10 - __half2float(__float2half(v10)),
                            v11 - __half2float(__float2half(v11)));
        pal[j][2] = pack_h2(v20 - __half2float(__float2half(v20)),
                            v21 - __half2float(__float2half(v21)));
        pal[j][3] = pack_h2(v30 - __half2float(__float2half(v30)),
                            v31 - __half2float(__float2half(v31)));
    }

    // ---- O = P V (m16 x n32 x k64) ----
    float o[4][4];
#pragma unroll
    for (int nt = 0; nt < 4; nt++)
#pragma unroll
        for (int id = 0; id < 4; id++) o[nt][id] = 0.f;

#pragma unroll
    for (int j = 0; j < 4; j++) {       // k16 tiles over keys
        uint32_t vh[2][4], vl[2][4];
#pragma unroll
        for (int t = 0; t < 2; t++) {
            uint32_t boff = (uint32_t)((t * 16 + b_row) * 144 + j * 32 + b_kb);
            ldsm_x4(vh[t], aVh + boff);
            ldsm_x4(vl[t], aVl + boff);
        }
        mma16816(o[0], pah[j], vh[0][0], vh[0][1]);
        mma16816(o[1], pah[j], vh[0][2], vh[0][3]);
        mma16816(o[2], pah[j], vh[1][0], vh[1][1]);
        mma16816(o[3], pah[j], vh[1][2], vh[1][3]);
        mma16816(o[0], pal[j], vh[0][0], vh[0][1]);
        mma16816(o[1], pal[j], vh[0][2], vh[0][3]);
        mma16816(o[2], pal[j], vh[1][0], vh[1][1]);
        mma16816(o[3], pal[j], vh[1][2], vh[1][3]);
        mma16816(o[0], pah[j], vl[0][0], vl[0][1]);
        mma16816(o[1], pah[j], vl[0][2], vl[0][3]);
        mma16816(o[2], pah[j], vl[1][0], vl[1][1]);
        mma16816(o[3], pah[j], vl[1][2], vl[1][3]);
    }

    // ---- write ctx fp16 hi/lo ----
    __half* chiw = g_chi + ((size_t)b * NTOK) * DIMV + h * HD;
    __half* clow = g_clo + ((size_t)b * NTOK) * DIMV + h * HD;
#pragma unroll
    for (int nt = 0; nt < 4; nt++) {
#pragma unroll
        for (int id = 0; id < 4; id++) {
            int q = r0 + 8 * (id >> 1);
            if (q >= NTOK) continue;
            int d = nt * 8 + c0 + (id & 1);
            float v = o[nt][id];
            __half hv = __float2half(v);
            chiw[(size_t)q * DIMV + d] = hv;
            clow[(size_t)q * DIMV + d] = __float2half(v - __half2float(hv));
        }
    }
}

// ============================================================================
extern "C" void kernel_launch(void* const* d_in, const int* in_sizes, int n_in,
                              void* d_out, int out_size)
{
    const float* x       = (const float*)d_in[0];
    const int*   mask    = (const int*)d_in[1];
    const float* qkv_w   = (const float*)d_in[2];
    const float* qkv_b   = (const float*)d_in[3];
    const float* proj_w  = (const float*)d_in[4];
    const float* proj_b  = (const float*)d_in[5];
    const float* rel_tbl = (const float*)d_in[6];
    float* out = (float*)d_out;

    __half *xhi, *xlo, *wq, *wp;
    cudaGetSymbolAddress((void**)&xhi, g_xhi);
    cudaGetSymbolAddress((void**)&xlo, g_xlo);
    cudaGetSymbolAddress((void**)&wq, g_wq);
    cudaGetSymbolAddress((void**)&wp, g_wp);

    constexpr int SMEMB = 2 * 3 * 128 * 80;    // 61440
    cudaFuncSetAttribute(mma_gemm<0>, cudaFuncAttributeMaxDynamicSharedMemorySize, SMEMB);
    cudaFuncSetAttribute(mma_gemm<1>, cudaFuncAttributeMaxDynamicSharedMemorySize, SMEMB);

    k_split_x<<<MTOT * 256 / 1024, 256>>>(x, xhi, xlo);
    k_split_w<<<768, 256>>>(qkv_w, wq, 768);
    k_split_w<<<256, 256>>>(proj_w, wp, 256);

    mma_gemm<0><<<dim3(6, MTOT / 128), 256, SMEMB>>>(qkv_b, nullptr);

    attn_kernel<<<BWIN * NH, 256>>>(mask, rel_tbl);

    mma_gemm<1><<<dim3(2, MTOT / 128), 256, SMEMB>>>(proj_b, out);
}

// round 15
// speedup vs baseline: 1.4294x; 1.0310x over previous
#include <cuda_runtime.h>
#include <cuda_fp16.h>
#include <cstdint>

#define BWIN 4096
#define NTOK 49
#define DIMV 256
#define NH   8
#define HD   32
#define MTOT (BWIN*NTOK)              /* 200704 */
#define QSCALE 0.17677669529663687f   /* 32^-0.5 */

// ================= scratch (device globals; no allocation allowed) =========
__device__ __half g_xhi[(size_t)MTOT * DIMV];
__device__ __half g_xlo[(size_t)MTOT * DIMV];
__device__ __half g_chi[(size_t)MTOT * DIMV];
__device__ __half g_clo[(size_t)MTOT * DIMV];
__device__ __half g_wq[768 * 256];
__device__ __half g_wp[256 * 256];
__device__ float g_Q[(size_t)BWIN * NH * NTOK * HD];
__device__ float g_K[(size_t)BWIN * NH * NTOK * HD];
__device__ float g_V[(size_t)BWIN * NH * NTOK * HD];

// ======================= helpers ===========================================
__device__ __forceinline__ uint32_t smem_u32(const void* p) {
    uint32_t a;
    asm("{ .reg .u64 t; cvta.to.shared.u64 t, %1; cvt.u32.u64 %0, t; }" : "=r"(a) : "l"(p));
    return a;
}
__device__ __forceinline__ void cp16(uint32_t sdst, const void* g) {
    asm volatile("cp.async.cg.shared.global [%0], [%1], 16;" :: "r"(sdst), "l"(g));
}
#define CP_COMMIT() asm volatile("cp.async.commit_group;" ::: "memory")

__device__ __forceinline__ void ldsm_x4(uint32_t (&r)[4], uint32_t addr) {
    asm volatile("ldmatrix.sync.aligned.m8n8.x4.shared.b16 {%0,%1,%2,%3}, [%4];"
                 : "=r"(r[0]), "=r"(r[1]), "=r"(r[2]), "=r"(r[3]) : "r"(addr));
}
__device__ __forceinline__ void mma16816(float (&d)[4], const uint32_t (&a)[4],
                                         uint32_t b0, uint32_t b1) {
    asm volatile("mma.sync.aligned.m16n8k16.row.col.f32.f16.f16.f32 "
                 "{%0,%1,%2,%3}, {%4,%5,%6,%7}, {%8,%9}, {%0,%1,%2,%3};"
                 : "+f"(d[0]), "+f"(d[1]), "+f"(d[2]), "+f"(d[3])
                 : "r"(a[0]), "r"(a[1]), "r"(a[2]), "r"(a[3]), "r"(b0), "r"(b1));
}
__device__ __forceinline__ uint32_t pack_h2(float x, float y) {
    __half2 h = __halves2half2(__float2half(x), __float2half(y));
    return *(uint32_t*)&h;
}

// ======================= split / pack kernels ==============================
__global__ __launch_bounds__(256) void k_split_x(const float* __restrict__ in,
                                                 __half* __restrict__ hi,
                                                 __half* __restrict__ lo) {
    size_t gi = ((size_t)blockIdx.x * 256 + threadIdx.x) * 4;
    float4 v = *(const float4*)(in + gi);
    __half h0 = __float2half(v.x), h1 = __float2half(v.y);
    __half h2 = __float2half(v.z), h3 = __float2half(v.w);
    __half l0 = __float2half(v.x - __half2float(h0));
    __half l1 = __float2half(v.y - __half2float(h1));
    __half l2 = __float2half(v.z - __half2float(h2));
    __half l3 = __float2half(v.w - __half2float(h3));
    *(__half2*)(hi + gi)     = __halves2half2(h0, h1);
    *(__half2*)(hi + gi + 2) = __halves2half2(h2, h3);
    *(__half2*)(lo + gi)     = __halves2half2(l0, l1);
    *(__half2*)(lo + gi + 2) = __halves2half2(l2, l3);
}

__global__ __launch_bounds__(256) void k_split_w(const float* __restrict__ w,
                                                 __half* __restrict__ hi, int N) {
    int i = blockIdx.x * 256 + threadIdx.x;
    int k = i / N, n = i - k * N;
    hi[(size_t)n * 256 + k] = __float2half(w[i]);
}

// ======================= HMMA GEMM (2-term fp16, 3-stage) ===================
template<int EPI>
__global__ __launch_bounds__(256, 2) void mma_gemm(const float* __restrict__ bias,
                                                   float* __restrict__ out) {
    extern __shared__ char smem[];
    const uint32_t sb = smem_u32(smem);
    constexpr int PITCH = 80;
    constexpr uint32_t TILE = 128 * PITCH;        // 10240 B
    constexpr uint32_t STAGE = 3 * TILE;          // Ahi, Alo, B = 30720 B
    constexpr int ITERS = 8;

    const int tid = threadIdx.x;
    const int wid = tid >> 5, lane = tid & 31;
    const int warp_m = wid & 1, warp_n = wid >> 1;

    const __half* gAh = (EPI ? g_chi : g_xhi) + (size_t)blockIdx.y * 128 * 256;
    const __half* gAl = (EPI ? g_clo : g_xlo) + (size_t)blockIdx.y * 128 * 256;
    const __half* gB  = (EPI ? g_wp  : g_wq)  + (size_t)blockIdx.x * 128 * 256;

    float acc[4][4][4];
#pragma unroll
    for (int a = 0; a < 4; a++)
#pragma unroll
        for (int b = 0; b < 4; b++)
#pragma unroll
            for (int c = 0; c < 4; c++) acc[a][b][c] = 0.f;

    const int lr = tid >> 2;
    const int lc = tid & 3;
    auto load_stage = [&](int it, int s) {
        const int k0 = it * 32;
        const uint32_t st = sb + (uint32_t)s * STAGE;
#pragma unroll
        for (int j = 0; j < 6; j++) {
            const __half* base = (j < 2) ? gAh : (j < 4) ? gAl : gB;
            int r = lr + (j & 1) * 64;
            cp16(st + (uint32_t)(j >> 1) * TILE + (uint32_t)(r * PITCH + lc * 16),
                 base + (size_t)r * 256 + k0 + lc * 8);
        }
        CP_COMMIT();
    };

    const int a_row = (lane & 7) + 8 * ((lane >> 3) & 1);
    const int a_kb  = ((lane >> 4) & 1) * 16;
    const int b_row = (lane & 7) + 8 * ((lane >> 4) & 1);
    const int b_kb  = ((lane >> 3) & 1) * 16;

    load_stage(0, 0);
    load_stage(1, 1);

#pragma unroll 1
    for (int it = 0; it < ITERS; ++it) {
        if (it + 1 < ITERS)
            asm volatile("cp.async.wait_group 1;" ::: "memory");
        else
            asm volatile("cp.async.wait_group 0;" ::: "memory");
        __syncthreads();
        if (it + 2 < ITERS) load_stage(it + 2, (it + 2) % 3);

        const int s = it % 3;
        const uint32_t sAh = sb + (uint32_t)s * STAGE;
        const uint32_t sAl = sAh + TILE;
        const uint32_t sB  = sAl + TILE;
#pragma unroll
        for (int h16 = 0; h16 < 2; h16++) {
            const int kb = h16 * 32;
            uint32_t bf[2][4];
#pragma unroll
            for (int np = 0; np < 2; np++) {
                uint32_t boff = (uint32_t)((warp_n * 32 + np * 16 + b_row) * PITCH + kb + b_kb);
                ldsm_x4(bf[np], sB + boff);
            }
            uint32_t ahi[4][4], alo[4][4];
#pragma unroll
            for (int mi = 0; mi < 4; mi++) {
                uint32_t aoff = (uint32_t)((warp_m * 64 + mi * 16 + a_row) * PITCH + kb + a_kb);
                ldsm_x4(ahi[mi], sAh + aoff);
                ldsm_x4(alo[mi], sAl + aoff);
            }
#pragma unroll
            for (int mi = 0; mi < 4; mi++) {
                mma16816(acc[mi][0], ahi[mi], bf[0][0], bf[0][1]);
                mma16816(acc[mi][1], ahi[mi], bf[0][2], bf[0][3]);
                mma16816(acc[mi][2], ahi[mi], bf[1][0], bf[1][1]);
                mma16816(acc[mi][3], ahi[mi], bf[1][2], bf[1][3]);
            }
#pragma unroll
            for (int mi = 0; mi < 4; mi++) {
                mma16816(acc[mi][0], alo[mi], bf[0][0], bf[0][1]);
                mma16816(acc[mi][1], alo[mi], bf[0][2], bf[0][3]);
                mma16816(acc[mi][2], alo[mi], bf[1][0], bf[1][1]);
                mma16816(acc[mi][3], alo[mi], bf[1][2], bf[1][3]);
            }
        }
    }

    const int row0 = blockIdx.y * 128 + warp_m * 64;
    const int col0 = blockIdx.x * 128 + warp_n * 32;

    if (EPI == 1) {
#pragma unroll
        for (int mi = 0; mi < 4; mi++) {
#pragma unroll
            for (int ni = 0; ni < 4; ni++) {
                int col = col0 + ni * 8 + (lane & 3) * 2;
                float bx0 = bias[col], bx1 = bias[col + 1];
                int r0 = row0 + mi * 16 + (lane >> 2);
                float2 v0 = make_float2(acc[mi][ni][0] + bx0, acc[mi][ni][1] + bx1);
                float2 v1 = make_float2(acc[mi][ni][2] + bx0, acc[mi][ni][3] + bx1);
                *(float2*)(out + (size_t)r0 * 256 + col)       = v0;
                *(float2*)(out + (size_t)(r0 + 8) * 256 + col) = v1;
            }
        }
    } else {
#pragma unroll
        for (int mi = 0; mi < 4; mi++) {
#pragma unroll
            for (int ni = 0; ni < 4; ni++) {
#pragma unroll
                for (int id = 0; id < 4; id++) {
                    int row = row0 + mi * 16 + (lane >> 2) + 8 * (id >> 1);
                    int col = col0 + ni * 8 + (lane & 3) * 2 + (id & 1);
                    float v = acc[mi][ni][id] + bias[col];
                    int s2 = col % 3;
                    int hd = col / 3;
                    int h = hd >> 5, d = hd & 31;
                    int b = row / 49, n = row - b * 49;
                    size_t addr = (size_t)(b * NH + h) * (NTOK * HD) + n * HD + d;
                    if (s2 == 0)      g_Q[addr] = v * QSCALE;
                    else if (s2 == 1) g_K[addr] = v;
                    else              g_V[addr] = v;
                }
            }
        }
    }
}

// ======================= attention v6: tensor-core, 2 heads/CTA =============
// One CTA = (window, head pair). 256 threads: all stage, warps 0-3 compute
// head 0, warps 4-7 compute head 1. Shared mask staging.
// dynamic smem layout (bytes):
//   0      sQh [2][64*40]h   10240
//   10240  sQl               10240
//   20480  sKh               10240
//   30720  sKl               10240
//   40960  sVTh [2][32*72]h   9216
//   50176  sVTl               9216
//   59392  sMask [2401]f      9616 (padded)
//   69008  sBias [2][172]f    1376
#define ATT_SMEM 70384
__global__ __launch_bounds__(256)
void attn_kernel(const int* __restrict__ mask, const float* __restrict__ bias_table)
{
    extern __shared__ char smem[];
    __half* sQh = (__half*)(smem);
    __half* sQl = (__half*)(smem + 10240);
    __half* sKh = (__half*)(smem + 20480);
    __half* sKl = (__half*)(smem + 30720);
    __half* sVTh = (__half*)(smem + 40960);
    __half* sVTl = (__half*)(smem + 50176);
    float* sMask = (float*)(smem + 59392);
    float* sBias = (float*)(smem + 69008);

    const int bx = blockIdx.x;
    const int b = bx >> 2, hbase = (bx & 3) << 1;
    const int tid = threadIdx.x;
    const int warp = tid >> 5, lane = tid & 31;

    const int* mbase = mask + (size_t)b * (NTOK * NTOK);

    // zero pads: Q/K rows 49..63 per head (300 uints each tile-head)
    for (int i = tid; i < 600; i += 256) {
        int head = i / 300, j = i - head * 300;
        int base = head * 1280 + 980 + j;       // tile = 2560 halfs = 1280 uints
        ((uint32_t*)sQh)[base] = 0; ((uint32_t*)sQl)[base] = 0;
        ((uint32_t*)sKh)[base] = 0; ((uint32_t*)sKl)[base] = 0;
    }
    for (int i = tid; i < 2304; i += 256) {     // VT tiles: 2 x 1152 uints
        ((uint32_t*)sVTh)[i] = 0; ((uint32_t*)sVTl)[i] = 0;
    }
    __syncthreads();

    // stage Q,K (hi/lo) + VT (hi/lo) for both heads
    for (int i = tid; i < 784; i += 256) {
        int head = (i >= 392);
        int j = i - head * 392;
        int r = j >> 3, c = (j & 7) << 2;
        size_t bhoff = (size_t)(b * NH + hbase + head) * (NTOK * HD);
        float4 q = ((const float4*)(g_Q + bhoff))[j];
        float4 k = ((const float4*)(g_K + bhoff))[j];
        float4 v = ((const float4*)(g_V + bhoff))[j];
        __half* qh = sQh + head * 2560; __half* ql = sQl + head * 2560;
        __half* kh = sKh + head * 2560; __half* kl = sKl + head * 2560;
        __half* vth = sVTh + head * 2304; __half* vtl = sVTl + head * 2304;

        __half qh0 = __float2half(q.x), qh1 = __float2half(q.y);
        __half qh2 = __float2half(q.z), qh3 = __float2half(q.w);
        *(__half2*)&qh[r * 40 + c]     = __halves2half2(qh0, qh1);
        *(__half2*)&qh[r * 40 + c + 2] = __halves2half2(qh2, qh3);
        *(__half2*)&ql[r * 40 + c] = __halves2half2(
            __float2half(q.x - __half2float(qh0)), __float2half(q.y - __half2float(qh1)));
        *(__half2*)&ql[r * 40 + c + 2] = __halves2half2(
            __float2half(q.z - __half2float(qh2)), __float2half(q.w - __half2float(qh3)));
        __half kh0 = __float2half(k.x), kh1 = __float2half(k.y);
        __half kh2 = __float2half(k.z), kh3 = __float2half(k.w);
        *(__half2*)&kh[r * 40 + c]     = __halves2half2(kh0, kh1);
        *(__half2*)&kh[r * 40 + c + 2] = __halves2half2(kh2, kh3);
        *(__half2*)&kl[r * 40 + c] = __halves2half2(
            __float2half(k.x - __half2float(kh0)), __float2half(k.y - __half2float(kh1)));
        *(__half2*)&kl[r * 40 + c + 2] = __halves2half2(
            __float2half(k.z - __half2float(kh2)), __float2half(k.w - __half2float(kh3)));
        float vv[4] = {v.x, v.y, v.z, v.w};
#pragma unroll
        for (int jj = 0; jj < 4; jj++) {
            __half hv = __float2half(vv[jj]);
            vth[(c + jj) * 72 + r] = hv;
            vtl[(c + jj) * 72 + r] = __float2half(vv[jj] - __half2float(hv));
        }
    }
    for (int i = tid; i < NTOK * NTOK; i += 256)
        sMask[i] = (1.0f - (float)mbase[i]) * (-1e10f);
    if (tid < 169) {
        sBias[tid]       = bias_table[tid * NH + hbase];
        sBias[172 + tid] = bias_table[tid * NH + hbase + 1];
    }
    __syncthreads();

    const int chead = warp >> 2;
    const int w4 = warp & 3;
    const uint32_t aQh = smem_u32(sQh + chead * 2560), aQl = smem_u32(sQl + chead * 2560);
    const uint32_t aKh = smem_u32(sKh + chead * 2560), aKl = smem_u32(sKl + chead * 2560);
    const uint32_t aVh = smem_u32(sVTh + chead * 2304), aVl = smem_u32(sVTl + chead * 2304);
    const float* bias_h = sBias + chead * 172;

    const int a_row = (lane & 7) + 8 * ((lane >> 3) & 1);
    const int a_kb  = ((lane >> 4) & 1) * 16;
    const int b_row = (lane & 7) + 8 * ((lane >> 4) & 1);
    const int b_kb  = ((lane >> 3) & 1) * 16;
    const int mrow = w4 * 16;

    // ---- S = Q K^T ----
    float s[8][4];
#pragma unroll
    for (int t = 0; t < 8; t++)
#pragma unroll
        for (int id = 0; id < 4; id++) s[t][id] = 0.f;

#pragma unroll
    for (int h16 = 0; h16 < 2; h16++) {
        uint32_t qh[4], ql[4];
        uint32_t aoff = (uint32_t)((mrow + a_row) * 80 + h16 * 32 + a_kb);
        ldsm_x4(qh, aQh + aoff);
        ldsm_x4(ql, aQl + aoff);
#pragma unroll
        for (int t = 0; t < 4; t++) {
            uint32_t kh[4], kl[4];
            uint32_t boff = (uint32_t)((t * 16 + b_row) * 80 + h16 * 32 + b_kb);
            ldsm_x4(kh, aKh + boff);
            ldsm_x4(kl, aKl + boff);
            mma16816(s[2 * t],     qh, kh[0], kh[1]);
            mma16816(s[2 * t + 1], qh, kh[2], kh[3]);
            mma16816(s[2 * t],     ql, kh[0], kh[1]);
            mma16816(s[2 * t + 1], ql, kh[2], kh[3]);
            mma16816(s[2 * t],     qh, kl[0], kl[1]);
            mma16816(s[2 * t + 1], qh, kl[2], kl[3]);
        }
    }

    // ---- bias + mask + oob ----
    const int r0 = mrow + (lane >> 2);
    const int c0 = (lane & 3) * 2;
#pragma unroll
    for (int t = 0; t < 8; t++) {
#pragma unroll
        for (int id = 0; id < 4; id++) {
            int q = r0 + 8 * (id >> 1);
            int k = 8 * t + c0 + (id & 1);
            if (k >= NTOK) { s[t][id] = -3.0e38f; continue; }
            if (q < NTOK) {
                int qi = q / 7, qj = q - qi * 7;
                int ki = k / 7, kj = k - ki * 7;
                s[t][id] += bias_h[(qi - ki + 6) * 13 + (qj - kj + 6)] + sMask[q * NTOK + k];
            }
        }
    }

    // ---- softmax in registers ----
    {
        float mx0 = -3.0e38f, mx1 = -3.0e38f;
#pragma unroll
        for (int t = 0; t < 8; t++) {
            mx0 = fmaxf(mx0, fmaxf(s[t][0], s[t][1]));
            mx1 = fmaxf(mx1, fmaxf(s[t][2], s[t][3]));
        }
#pragma unroll
        for (int off = 1; off <= 2; off <<= 1) {
            mx0 = fmaxf(mx0, __shfl_xor_sync(0xffffffffu, mx0, off));
            mx1 = fmaxf(mx1, __shfl_xor_sync(0xffffffffu, mx1, off));
        }
        float sum0 = 0.f, sum1 = 0.f;
#pragma unroll
        for (int t = 0; t < 8; t++) {
            s[t][0] = __expf(s[t][0] - mx0); sum0 += s[t][0];
            s[t][1] = __expf(s[t][1] - mx0); sum0 += s[t][1];
            s[t][2] = __expf(s[t][2] - mx1); sum1 += s[t][2];
            s[t][3] = __expf(s[t][3] - mx1); sum1 += s[t][3];
        }
#pragma unroll
        for (int off = 1; off <= 2; off <<= 1) {
            sum0 += __shfl_xor_sync(0xffffffffu, sum0, off);
            sum1 += __shfl_xor_sync(0xffffffffu, sum1, off);
        }
        float i0 = 1.0f / sum0, i1 = 1.0f / sum1;
#pragma unroll
        for (int t = 0; t < 8; t++) {
            s[t][0] *= i0; s[t][1] *= i0;
            s[t][2] *= i1; s[t][3] *= i1;
        }
    }

    // ---- pack P hi/lo into A-fragments ----
    uint32_t pah[4][4], pal[4][4];
#pragma unroll
    for (int j = 0; j < 4; j++) {
        float v00 = s[2 * j][0],     v01 = s[2 * j][1];
        float v10 = s[2 * j][2],     v11 = s[2 * j][3];
        float v20 = s[2 * j + 1][0], v21 = s[2 * j + 1][1];
        float v30 = s[2 * j + 1][2], v31 = s[2 * j + 1][3];
        pah[j][0] = pack_h2(v00, v01);
        pah[j][1] = pack_h2(v10, v11);
        pah[j][2] = pack_h2(v20, v21);
        pah[j][3] = pack_h2(v30, v31);
        pal[j][0] = pack_h2(v00 - __half2float(__float2half(v00)),
                            v01 - __half2float(__float2half(v01)));
        pal[j][1] = pack_h2(v10 - __half2float(__float2half(v10)),
                            v11 - __half2float(__float2half(v11)));
        pal[j][2] = pack_h2(v20 - __half2float(__float2half(v20)),
                            v21 - __half2float(__float2half(v21)));
        pal[j][3] = pack_h2(v30 - __half2float(__float2half(v30)),
                            v31 - __half2float(__float2half(v31)));
    }

    // ---- O = P V ----
    float o[4][4];
#pragma unroll
    for (int nt = 0; nt < 4; nt++)
#pragma unroll
        for (int id = 0; id < 4; id++) o[nt][id] = 0.f;

#pragma unroll
    for (int j = 0; j < 4; j++) {
        uint32_t vh[2][4], vl[2][4];
#pragma unroll
        for (int t = 0; t < 2; t++) {
            uint32_t boff = (uint32_t)((t * 16 + b_row) * 144 + j * 32 + b_kb);
            ldsm_x4(vh[t], aVh + boff);
            ldsm_x4(vl[t], aVl + boff);
        }
        mma16816(o[0], pah[j], vh[0][0], vh[0][1]);
        mma16816(o[1], pah[j], vh[0][2], vh[0][3]);
        mma16816(o[2], pah[j], vh[1][0], vh[1][1]);
        mma16816(o[3], pah[j], vh[1][2], vh[1][3]);
        mma16816(o[0], pal[j], vh[0][0], vh[0][1]);
        mma16816(o[1], pal[j], vh[0][2], vh[0][3]);
        mma16816(o[2], pal[j], vh[1][0], vh[1][1]);
        mma16816(o[3], pal[j], vh[1][2], vh[1][3]);
        mma16816(o[0], pah[j], vl[0][0], vl[0][1]);
        mma16816(o[1], pah[j], vl[0][2], vl[0][3]);
        mma16816(o[2], pah[j], vl[1][0], vl[1][1]);
        mma16816(o[3], pah[j], vl[1][2], vl[1][3]);
    }

    // ---- write ctx fp16 hi/lo ----
    const int h = hbase + chead;
    __half* chiw = g_chi + ((size_t)b * NTOK) * DIMV + h * HD;
    __half* clow = g_clo + ((size_t)b * NTOK) * DIMV + h * HD;
#pragma unroll
    for (int nt = 0; nt < 4; nt++) {
#pragma unroll
        for (int id = 0; id < 4; id++) {
            int q = r0 + 8 * (id >> 1);
            if (q >= NTOK) continue;
            int d = nt * 8 + c0 + (id & 1);
            float v = o[nt][id];
            __half hv = __float2half(v);
            chiw[(size_t)q * DIMV + d] = hv;
            clow[(size_t)q * DIMV + d] = __float2half(v - __half2float(hv));
        }
    }
}

// ============================================================================
extern "C" void kernel_launch(void* const* d_in, const int* in_sizes, int n_in,
                              void* d_out, int out_size)
{
    const float* x       = (const float*)d_in[0];
    const int*   mask    = (const int*)d_in[1];
    const float* qkv_w   = (const float*)d_in[2];
    const float* qkv_b   = (const float*)d_in[3];
    const float* proj_w  = (const float*)d_in[4];
    const float* proj_b  = (const float*)d_in[5];
    const float* rel_tbl = (const float*)d_in[6];
    float* out = (float*)d_out;

    __half *xhi, *xlo, *wq, *wp;
    cudaGetSymbolAddress((void**)&xhi, g_xhi);
    cudaGetSymbolAddress((void**)&xlo, g_xlo);
    cudaGetSymbolAddress((void**)&wq, g_wq);
    cudaGetSymbolAddress((void**)&wp, g_wp);

    constexpr int SMEMB = 3 * 3 * 128 * 80;    // 92160 (3 stages x 30720)
    cudaFuncSetAttribute(mma_gemm<0>, cudaFuncAttributeMaxDynamicSharedMemorySize, SMEMB);
    cudaFuncSetAttribute(mma_gemm<1>, cudaFuncAttributeMaxDynamicSharedMemorySize, SMEMB);
    cudaFuncSetAttribute(attn_kernel, cudaFuncAttributeMaxDynamicSharedMemorySize, ATT_SMEM);

    k_split_x<<<MTOT * 256 / 1024, 256>>>(x, xhi, xlo);
    k_split_w<<<768, 256>>>(qkv_w, wq, 768);
    k_split_w<<<256, 256>>>(proj_w, wp, 256);

    mma_gemm<0><<<dim3(6, MTOT / 128), 256, SMEMB>>>(qkv_b, nullptr);

    attn_kernel<<<BWIN * 4, 256, ATT_SMEM>>>(mask, rel_tbl);

    mma_gemm<1><<<dim3(2, MTOT / 128), 256, SMEMB>>>(proj_b, out);
}